// round 4
// baseline (speedup 1.0000x reference)
#include <cuda_runtime.h>
#include <cuda_bf16.h>

#define NB 32
#define HW 16384
#define NC 25   // spectral coefficients: (0,0), (0,1..3), (mu=1..3 x nu=-3..3)

// Packed per-b evaluation constants: 14 float4 per b.
__device__ float4 g_C[NB][14];

__device__ __forceinline__ float2 cmul(float2 a, float2 b) {
    return make_float2(fmaf(a.x, b.x, -a.y * b.y), fmaf(a.x, b.y, a.y * b.x));
}
__device__ __forceinline__ float2 cadd(float2 a, float2 b) {
    return make_float2(a.x + b.x, a.y + b.y);
}

// ---------------------------------------------------------------------------
// One-block prep kernel (512 threads).
// Phase 1: threads 0..127 build the 4 ansatz-block unitaries per b (s=0..3);
//          s==0 stores only column 0 (v_init), s>0 stores the full matrix.
// Phase 2: 16 threads per b evolve the polynomial amplitudes
//          a_r[m][n] (coefficients of E0^m E1^n) through 3 stages of
//          (diag shift, 4x4 matvec).
// Phase 3: 16 threads per b compute the 25 spectral coefficients
//          c_{mu,nu} = sum_r s_r sum a_r[m][n] conj(a_r[m-mu][n-nu]).
// Phase 4: 14 threads per b pack folded constants into g_C.
// ---------------------------------------------------------------------------
__global__ void qprep_all(const float* __restrict__ qs) {
    __shared__ float2 sV[NB][4];
    __shared__ float2 sU[NB][3][4][4];
    __shared__ float2 sA[NB][4][16];   // [b][comp r][slot = m*4+n]
    __shared__ float2 sCC[NB][NC];

    const int t = threadIdx.x;

    // ---- Phase 1: build unitaries ----
    if (t < NB * 4) {
        int b = t >> 2;
        int s = t & 3;

        float2 M[4][4];
#pragma unroll
        for (int r = 0; r < 4; r++)
#pragma unroll
            for (int c = 0; c < 4; c++)
                M[r][c] = make_float2((r == c) ? 1.0f : 0.0f, 0.0f);

#pragma unroll
        for (int j = 0; j < 2; j++) {           // ANSATZ layers
#pragma unroll
            for (int k = 0; k < 2; k++) {       // wires
                const float* p = qs + ((((b * 4 + s) * 2 + j) * 2 + k) * 3);
                float th = p[0], ph = p[1], la = p[2];
                float ct = cosf(th * 0.5f);
                float st = sinf(th * 0.5f);
                float sl, cl, sp, cp;
                sincosf(la, &sl, &cl);
                sincosf(ph, &sp, &cp);
                float2 g00 = make_float2(ct, 0.0f);
                float2 g01 = make_float2(-cl * st, -sl * st);
                float2 g10 = make_float2(cp * st, sp * st);
                float2 epl = cmul(make_float2(cp, sp), make_float2(cl, sl));
                float2 g11 = make_float2(epl.x * ct, epl.y * ct);

                if (k == 0) {
                    // wire 0 (MSB): row pairs (0,2),(1,3)
#pragma unroll
                    for (int c = 0; c < 4; c++) {
                        float2 a0 = M[0][c], a1 = M[2][c];
                        M[0][c] = cadd(cmul(g00, a0), cmul(g01, a1));
                        M[2][c] = cadd(cmul(g10, a0), cmul(g11, a1));
                        float2 b0 = M[1][c], b1 = M[3][c];
                        M[1][c] = cadd(cmul(g00, b0), cmul(g01, b1));
                        M[3][c] = cadd(cmul(g10, b0), cmul(g11, b1));
                    }
                } else {
                    // wire 1 (LSB): row pairs (0,1),(2,3)
#pragma unroll
                    for (int c = 0; c < 4; c++) {
                        float2 a0 = M[0][c], a1 = M[1][c];
                        M[0][c] = cadd(cmul(g00, a0), cmul(g01, a1));
                        M[1][c] = cadd(cmul(g10, a0), cmul(g11, a1));
                        float2 b0 = M[2][c], b1 = M[3][c];
                        M[2][c] = cadd(cmul(g00, b0), cmul(g01, b1));
                        M[3][c] = cadd(cmul(g10, b0), cmul(g11, b1));
                    }
                }
            }
            // CNOT(ctrl=wire0): swap rows 2,3
#pragma unroll
            for (int c = 0; c < 4; c++) {
                float2 tmp = M[2][c]; M[2][c] = M[3][c]; M[3][c] = tmp;
            }
        }

        if (s == 0) {
#pragma unroll
            for (int r = 0; r < 4; r++) sV[b][r] = M[r][0];
        } else {
#pragma unroll
            for (int r = 0; r < 4; r++)
#pragma unroll
                for (int c = 0; c < 4; c++)
                    sU[b][s - 1][r][c] = M[r][c];
        }
    }
    __syncthreads();

    // ---- Phase 2: polynomial evolution ----
    const int b    = t >> 4;
    const int slot = t & 15;
    const int m    = slot >> 2;
    const int n    = slot & 3;
    const float2 zero = make_float2(0.0f, 0.0f);

#pragma unroll
    for (int r = 0; r < 4; r++)
        sA[b][r][slot] = (slot == 0) ? sV[b][r] : zero;
    __syncthreads();

    for (int i = 0; i < 3; i++) {
        // diag shift: comp0 (0,0), comp1 (0,+1), comp2 (+1,0), comp3 (+1,+1)
        float2 sh0 = sA[b][0][slot];
        float2 sh1 = (n >= 1) ? sA[b][1][slot - 1] : zero;
        float2 sh2 = (m >= 1) ? sA[b][2][slot - 4] : zero;
        float2 sh3 = (m >= 1 && n >= 1) ? sA[b][3][slot - 5] : zero;
        __syncthreads();
        float2 nv[4];
#pragma unroll
        for (int r = 0; r < 4; r++) {
            float2 acc = cmul(sU[b][i][r][0], sh0);
            acc = cadd(acc, cmul(sU[b][i][r][1], sh1));
            acc = cadd(acc, cmul(sU[b][i][r][2], sh2));
            acc = cadd(acc, cmul(sU[b][i][r][3], sh3));
            nv[r] = acc;
        }
#pragma unroll
        for (int r = 0; r < 4; r++) sA[b][r][slot] = nv[r];
        __syncthreads();
    }

    // ---- Phase 3: spectral coefficients ----
    for (int kk = slot; kk < NC; kk += 16) {
        int mu, nu;
        if (kk == 0)      { mu = 0; nu = 0; }
        else if (kk < 4)  { mu = 0; nu = kk; }
        else              { mu = 1 + (kk - 4) / 7; nu = (kk - 4) % 7 - 3; }

        int mlo = (mu > 0) ? mu : 0;
        int nlo = (nu > 0) ? nu : 0;
        int nhi = (nu < 0) ? (3 + nu) : 3;

        float2 acc = zero;
        for (int r = 0; r < 4; r++) {
            float sgn = (r < 2) ? 1.0f : -1.0f;
            for (int mm = mlo; mm <= 3; mm++) {
                for (int nn = nlo; nn <= nhi; nn++) {
                    float2 a  = sA[b][r][mm * 4 + nn];
                    float2 bb = sA[b][r][(mm - mu) * 4 + (nn - nu)];
                    // acc += sgn * a * conj(bb)
                    acc.x += sgn * (a.x * bb.x + a.y * bb.y);
                    acc.y += sgn * (a.y * bb.x - a.x * bb.y);
                }
            }
        }
        sCC[b][kk] = acc;
    }
    __syncthreads();

    // ---- Phase 4: pack folded constants ----
    // Layout (floats): [c00, 2c01.x, 2c01.y, 2c02.x][2c02.y, 2c03.x, 2c03.y, 0]
    // per mu=1..3 (base = 2 + (mu-1)*4):
    //   [2cm0.x, 2cm0.y, P1.x, P1.y][Q1.x, Q1.y, P2.x, P2.y]
    //   [Q2.x, Q2.y, P3.x, P3.y][Q3.x, Q3.y, 0, 0]
    // P = 2(c+ + c-), Q = 2i(c+ - c-)  => Q.x = -2(c+.y - c-.y), Q.y = 2(c+.x - c-.x)
    if (slot < 14) {
        float4 o;
        if (slot == 0) {
            o = make_float4(sCC[b][0].x, 2.f * sCC[b][1].x, 2.f * sCC[b][1].y, 2.f * sCC[b][2].x);
        } else if (slot == 1) {
            o = make_float4(2.f * sCC[b][2].y, 2.f * sCC[b][3].x, 2.f * sCC[b][3].y, 0.f);
        } else {
            int mu = 1 + (slot - 2) / 4;
            int j  = (slot - 2) & 3;
            int base = 4 + (mu - 1) * 7 + 3;  // index of c_{mu,0}
            float2 c0 = sCC[b][base];
            float2 c1p = sCC[b][base + 1], c1m = sCC[b][base - 1];
            float2 c2p = sCC[b][base + 2], c2m = sCC[b][base - 2];
            float2 c3p = sCC[b][base + 3], c3m = sCC[b][base - 3];
            if (j == 0) {
                o = make_float4(2.f * c0.x, 2.f * c0.y,
                                2.f * (c1p.x + c1m.x), 2.f * (c1p.y + c1m.y));
            } else if (j == 1) {
                o = make_float4(-2.f * (c1p.y - c1m.y), 2.f * (c1p.x - c1m.x),
                                 2.f * (c2p.x + c2m.x), 2.f * (c2p.y + c2m.y));
            } else if (j == 2) {
                o = make_float4(-2.f * (c2p.y - c2m.y), 2.f * (c2p.x - c2m.x),
                                 2.f * (c3p.x + c3m.x), 2.f * (c3p.y + c3m.y));
            } else {
                o = make_float4(-2.f * (c3p.y - c3m.y), 2.f * (c3p.x - c3m.x), 0.f, 0.f);
            }
        }
        g_C[b][slot] = o;
    }
}

// ---------------------------------------------------------------------------
// Main kernel: evaluate the trig polynomial per pixel.
// ---------------------------------------------------------------------------
__global__ void __launch_bounds__(256, 8)
qmain_kernel(const float* __restrict__ x, float* __restrict__ out) {
    __shared__ float4 sC[14];
    const int b = blockIdx.y;
    if (threadIdx.x < 14) sC[threadIdx.x] = g_C[b][threadIdx.x];
    __syncthreads();

    const int h = blockIdx.x * blockDim.x + threadIdx.x;
    float2 xv = reinterpret_cast<const float2*>(x)[b * HW + h];

    float A1y, A1x, B1y, B1x;
    __sincosf(xv.x, &A1y, &A1x);   // A1 = e^{i x0}
    __sincosf(xv.y, &B1y, &B1x);   // B1 = e^{i x1}

    float A2x = fmaf(A1x, A1x, -A1y * A1y);
    float A2y = 2.0f * A1x * A1y;
    float A3x = fmaf(A2x, A1x, -A2y * A1y);
    float A3y = fmaf(A2x, A1y,  A2y * A1x);
    float B2x = fmaf(B1x, B1x, -B1y * B1y);
    float B2y = 2.0f * B1x * B1y;
    float B3x = fmaf(B2x, B1x, -B2y * B1y);
    float B3y = fmaf(B2x, B1y,  B2y * B1x);

    float4 q0 = sC[0], q1 = sC[1];
    float ev = q0.x;
    ev = fmaf(q0.y, B1x, ev); ev = fmaf(-q0.z, B1y, ev);
    ev = fmaf(q0.w, B2x, ev); ev = fmaf(-q1.x, B2y, ev);
    ev = fmaf(q1.y, B3x, ev); ev = fmaf(-q1.z, B3y, ev);

#pragma unroll
    for (int mu = 0; mu < 3; mu++) {
        float4 r0 = sC[2 + mu * 4 + 0];
        float4 r1 = sC[2 + mu * 4 + 1];
        float4 r2 = sC[2 + mu * 4 + 2];
        float4 r3 = sC[2 + mu * 4 + 3];
        float Tx = r0.x, Ty = r0.y;
        Tx = fmaf(r0.z, B1x, Tx); Tx = fmaf(r1.x, B1y, Tx);
        Ty = fmaf(r0.w, B1x, Ty); Ty = fmaf(r1.y, B1y, Ty);
        Tx = fmaf(r1.z, B2x, Tx); Tx = fmaf(r2.x, B2y, Tx);
        Ty = fmaf(r1.w, B2x, Ty); Ty = fmaf(r2.y, B2y, Ty);
        Tx = fmaf(r2.z, B3x, Tx); Tx = fmaf(r3.x, B3y, Tx);
        Ty = fmaf(r2.w, B3x, Ty); Ty = fmaf(r3.y, B3y, Ty);
        float Ax = (mu == 0) ? A1x : (mu == 1) ? A2x : A3x;
        float Ay = (mu == 0) ? A1y : (mu == 1) ? A2y : A3y;
        ev = fmaf(Ax, Tx, ev);
        ev = fmaf(-Ay, Ty, ev);
    }

    out[b * HW + h] = ev;
}

extern "C" void kernel_launch(void* const* d_in, const int* in_sizes, int n_in,
                              void* d_out, int out_size) {
    const float* x  = (const float*)d_in[0];   // (32, 16384, 2) float32
    const float* qs = (const float*)d_in[1];   // (32, 4, 2, 2, 3) float32
    float* out = (float*)d_out;                // (32, 16384) float32

    qprep_all<<<1, 512>>>(qs);

    dim3 grid(HW / 256, NB);
    qmain_kernel<<<grid, 256>>>(x, out);
}

// round 5
// speedup vs baseline: 1.5619x; 1.5619x over previous
#include <cuda_runtime.h>
#include <cuda_bf16.h>

#define NB 32
#define HW 16384
#define NC 25

// Duplicated, sign-folded per-b constants: 56 entries, each float2(v, v).
// Old-float-layout index == entry index (see qprep phase 4).
__device__ float2 g_C2[NB][56];

__device__ __forceinline__ float2 cmul(float2 a, float2 b) {
    return make_float2(fmaf(a.x, b.x, -a.y * b.y), fmaf(a.x, b.y, a.y * b.x));
}
__device__ __forceinline__ float2 cadd(float2 a, float2 b) {
    return make_float2(a.x + b.x, a.y + b.y);
}

// ---- f32x2 packed helpers (sm_103a FFMA2 path; ptxas won't auto-generate) ----
typedef unsigned long long u64;
__device__ __forceinline__ u64 pk2(float lo, float hi) {
    u64 r; asm("mov.b64 %0, {%1,%2};" : "=l"(r) : "f"(lo), "f"(hi)); return r;
}
__device__ __forceinline__ u64 fma2(u64 a, u64 b, u64 c) {
    u64 d; asm("fma.rn.f32x2 %0, %1, %2, %3;" : "=l"(d) : "l"(a), "l"(b), "l"(c)); return d;
}
__device__ __forceinline__ u64 mul2(u64 a, u64 b) {
    u64 d; asm("mul.rn.f32x2 %0, %1, %2;" : "=l"(d) : "l"(a), "l"(b)); return d;
}
__device__ __forceinline__ u64 add2(u64 a, u64 b) {
    u64 d; asm("add.rn.f32x2 %0, %1, %2;" : "=l"(d) : "l"(a), "l"(b)); return d;
}
__device__ __forceinline__ void upk2(u64 v, float& lo, float& hi) {
    asm("mov.b64 {%0,%1}, %2;" : "=f"(lo), "=f"(hi) : "l"(v));
}

// ---------------------------------------------------------------------------
// Prep: one block per b, 32 threads. Fast-math trig (tolerance is 1e-3; we
// have ~3 orders of margin).
// Phase 1 (t<4): build ansatz-block unitaries (s=t); s==0 keeps only col 0.
// Phase 2 (t<16): evolve polynomial amplitudes a_r[m][n] through 3 stages.
// Phase 3 (t<25): spectral coefficients c_{mu,nu}.
// Phase 4: pack 56 sign-folded floats, duplicated into float2, to g_C2.
// ---------------------------------------------------------------------------
__global__ void qprep(const float* __restrict__ qs) {
    __shared__ float2 sV[4];
    __shared__ float2 sU[3][4][4];
    __shared__ float2 sA[4][16];
    __shared__ float2 sCC[NC];

    const int b = blockIdx.x;
    const int t = threadIdx.x;
    const float2 zero = make_float2(0.0f, 0.0f);

    // ---- Phase 1 ----
    if (t < 4) {
        const int s = t;
        float2 M[4][4];
#pragma unroll
        for (int r = 0; r < 4; r++)
#pragma unroll
            for (int c = 0; c < 4; c++)
                M[r][c] = make_float2((r == c) ? 1.0f : 0.0f, 0.0f);

#pragma unroll
        for (int j = 0; j < 2; j++) {
#pragma unroll
            for (int k = 0; k < 2; k++) {
                const float* p = qs + ((((b * 4 + s) * 2 + j) * 2 + k) * 3);
                float th = p[0], ph = p[1], la = p[2];
                float ct = __cosf(th * 0.5f);
                float st = __sinf(th * 0.5f);
                float sl, cl, sp, cp;
                __sincosf(la, &sl, &cl);
                __sincosf(ph, &sp, &cp);
                float2 g00 = make_float2(ct, 0.0f);
                float2 g01 = make_float2(-cl * st, -sl * st);
                float2 g10 = make_float2(cp * st, sp * st);
                float2 epl = cmul(make_float2(cp, sp), make_float2(cl, sl));
                float2 g11 = make_float2(epl.x * ct, epl.y * ct);

                if (k == 0) {
#pragma unroll
                    for (int c = 0; c < 4; c++) {
                        float2 a0 = M[0][c], a1 = M[2][c];
                        M[0][c] = cadd(cmul(g00, a0), cmul(g01, a1));
                        M[2][c] = cadd(cmul(g10, a0), cmul(g11, a1));
                        float2 b0 = M[1][c], b1 = M[3][c];
                        M[1][c] = cadd(cmul(g00, b0), cmul(g01, b1));
                        M[3][c] = cadd(cmul(g10, b0), cmul(g11, b1));
                    }
                } else {
#pragma unroll
                    for (int c = 0; c < 4; c++) {
                        float2 a0 = M[0][c], a1 = M[1][c];
                        M[0][c] = cadd(cmul(g00, a0), cmul(g01, a1));
                        M[1][c] = cadd(cmul(g10, a0), cmul(g11, a1));
                        float2 b0 = M[2][c], b1 = M[3][c];
                        M[2][c] = cadd(cmul(g00, b0), cmul(g01, b1));
                        M[3][c] = cadd(cmul(g10, b0), cmul(g11, b1));
                    }
                }
            }
#pragma unroll
            for (int c = 0; c < 4; c++) {
                float2 tmp = M[2][c]; M[2][c] = M[3][c]; M[3][c] = tmp;
            }
        }

        if (s == 0) {
#pragma unroll
            for (int r = 0; r < 4; r++) sV[r] = M[r][0];
        } else {
#pragma unroll
            for (int r = 0; r < 4; r++)
#pragma unroll
                for (int c = 0; c < 4; c++)
                    sU[s - 1][r][c] = M[r][c];
        }
    }
    __syncthreads();

    // ---- Phase 2 ----
    const int slot = t;
    const int m = slot >> 2;
    const int n = slot & 3;

    if (t < 16) {
#pragma unroll
        for (int r = 0; r < 4; r++)
            sA[r][slot] = (slot == 0) ? sV[r] : zero;
    }
    __syncthreads();

    for (int i = 0; i < 3; i++) {
        float2 sh0 = zero, sh1 = zero, sh2 = zero, sh3 = zero;
        if (t < 16) {
            sh0 = sA[0][slot];
            if (n >= 1) sh1 = sA[1][slot - 1];
            if (m >= 1) sh2 = sA[2][slot - 4];
            if (m >= 1 && n >= 1) sh3 = sA[3][slot - 5];
        }
        __syncthreads();
        if (t < 16) {
            float2 nv[4];
#pragma unroll
            for (int r = 0; r < 4; r++) {
                float2 acc = cmul(sU[i][r][0], sh0);
                acc = cadd(acc, cmul(sU[i][r][1], sh1));
                acc = cadd(acc, cmul(sU[i][r][2], sh2));
                acc = cadd(acc, cmul(sU[i][r][3], sh3));
                nv[r] = acc;
            }
#pragma unroll
            for (int r = 0; r < 4; r++) sA[r][slot] = nv[r];
        }
        __syncthreads();
    }

    // ---- Phase 3 ----
    if (t < NC) {
        int mu, nu;
        if (t == 0)      { mu = 0; nu = 0; }
        else if (t < 4)  { mu = 0; nu = t; }
        else             { mu = 1 + (t - 4) / 7; nu = (t - 4) % 7 - 3; }

        int mlo = (mu > 0) ? mu : 0;
        int nlo = (nu > 0) ? nu : 0;
        int nhi = (nu < 0) ? (3 + nu) : 3;

        float2 acc = zero;
        for (int r = 0; r < 4; r++) {
            float sgn = (r < 2) ? 1.0f : -1.0f;
            for (int mm = mlo; mm <= 3; mm++) {
                for (int nn = nlo; nn <= nhi; nn++) {
                    float2 a  = sA[r][mm * 4 + nn];
                    float2 bb = sA[r][(mm - mu) * 4 + (nn - nu)];
                    acc.x += sgn * (a.x * bb.x + a.y * bb.y);
                    acc.y += sgn * (a.y * bb.x - a.x * bb.y);
                }
            }
        }
        sCC[t] = acc;
    }
    __syncthreads();

    // ---- Phase 4: sign-folded, duplicated table ----
    // floats 0..7:  c00, 2c01.x, -2c01.y, 2c02.x, -2c02.y, 2c03.x, -2c03.y, 0
    // per mu (base=8+16*mu4): 2cm0.x, 2cm0.y, P1x,P1y, Q1x,Q1y, P2x,P2y,
    //                          Q2x,Q2y, P3x,P3y, Q3x,Q3y, 0, 0
    // P = 2(c+ + c-); Qx = -2(c+.y - c-.y); Qy = 2(c+.x - c-.x)
    for (int idx = t; idx < 56; idx += 32) {
        float v;
        if (idx == 0) {
            v = sCC[0].x;
        } else if (idx == 7) {
            v = 0.0f;
        } else if (idx < 7) {
            int k = (idx + 1) >> 1;
            v = (idx & 1) ? (2.0f * sCC[k].x) : (-2.0f * sCC[k].y);
        } else {
            int j = idx - 8;
            int mu4 = j >> 4;
            int r = j & 15;
            int base = 4 + mu4 * 7 + 3;   // index of c_{mu,0} in sCC
            if (r == 0)      v = 2.0f * sCC[base].x;
            else if (r == 1) v = 2.0f * sCC[base].y;
            else if (r < 14) {
                int nu = (r - 2) / 4 + 1;
                int type = (r - 2) & 3;
                float2 cp = sCC[base + nu], cm = sCC[base - nu];
                if (type == 0)      v = 2.0f * (cp.x + cm.x);   // Px
                else if (type == 1) v = 2.0f * (cp.y + cm.y);   // Py
                else if (type == 2) v = -2.0f * (cp.y - cm.y);  // Qx
                else                v = 2.0f * (cp.x - cm.x);   // Qy
            } else {
                v = 0.0f;
            }
        }
        g_C2[b][idx] = make_float2(v, v);
    }
}

// ---------------------------------------------------------------------------
// Main: 2 pixels per thread, f32x2 SIMD across the pixel pair.
// grid = (HW/512, NB), block = 256.
// ---------------------------------------------------------------------------
__global__ void __launch_bounds__(256)
qmain_kernel(const float* __restrict__ x, float* __restrict__ out) {
    __shared__ float2 sC[56];
    const int b = blockIdx.y;
    if (threadIdx.x < 28)
        ((float4*)sC)[threadIdx.x] = ((const float4*)&g_C2[b][0])[threadIdx.x];
    __syncthreads();
    const u64* C = (const u64*)sC;

    const int idx = blockIdx.x * blockDim.x + threadIdx.x;     // pixel-pair index
    float4 xx = reinterpret_cast<const float4*>(x)[b * (HW / 2) + idx];

    float a0s, a0c, b0s, b0c, a1s, a1c, b1s, b1c;
    __sincosf(xx.x, &a0s, &a0c);
    __sincosf(xx.y, &b0s, &b0c);
    __sincosf(xx.z, &a1s, &a1c);
    __sincosf(xx.w, &b1s, &b1c);

    u64 A1x = pk2(a0c, a1c), A1y = pk2(a0s, a1s);
    u64 B1x = pk2(b0c, b1c), B1y = pk2(b0s, b1s);
    const u64 NEG1 = pk2(-1.0f, -1.0f);

    u64 nA1y = mul2(A1y, NEG1);
    u64 nB1y = mul2(B1y, NEG1);

    // powers: E^2, E^3 for A and B
    u64 A2x = fma2(A1x, A1x, mul2(A1y, nA1y));
    u64 tA  = mul2(A1x, A1y);
    u64 A2y = add2(tA, tA);
    u64 A3x = fma2(A2x, A1x, mul2(A2y, nA1y));
    u64 A3y = fma2(A2x, A1y, mul2(A2y, A1x));

    u64 B2x = fma2(B1x, B1x, mul2(B1y, nB1y));
    u64 tB  = mul2(B1x, B1y);
    u64 B2y = add2(tB, tB);
    u64 B3x = fma2(B2x, B1x, mul2(B2y, nB1y));
    u64 B3y = fma2(B2x, B1y, mul2(B2y, B1x));

    u64 nA2y = mul2(A2y, NEG1);
    u64 nA3y = mul2(A3y, NEG1);

    // mu = 0 row (B-only terms); sin-coefficients pre-negated in table
    u64 ev = C[0];
    ev = fma2(C[1], B1x, ev);
    ev = fma2(C[2], B1y, ev);
    ev = fma2(C[3], B2x, ev);
    ev = fma2(C[4], B2y, ev);
    ev = fma2(C[5], B3x, ev);
    ev = fma2(C[6], B3y, ev);

#pragma unroll
    for (int mu4 = 0; mu4 < 3; mu4++) {
        const u64* R = C + 8 + mu4 * 16;
        u64 Tx = R[0];
        Tx = fma2(R[2],  B1x, Tx);
        Tx = fma2(R[4],  B1y, Tx);
        Tx = fma2(R[6],  B2x, Tx);
        Tx = fma2(R[8],  B2y, Tx);
        Tx = fma2(R[10], B3x, Tx);
        Tx = fma2(R[12], B3y, Tx);
        u64 Ty = R[1];
        Ty = fma2(R[3],  B1x, Ty);
        Ty = fma2(R[5],  B1y, Ty);
        Ty = fma2(R[7],  B2x, Ty);
        Ty = fma2(R[9],  B2y, Ty);
        Ty = fma2(R[11], B3x, Ty);
        Ty = fma2(R[13], B3y, Ty);

        u64 Ax  = (mu4 == 0) ? A1x  : (mu4 == 1) ? A2x  : A3x;
        u64 nAy = (mu4 == 0) ? nA1y : (mu4 == 1) ? nA2y : nA3y;
        ev = fma2(Ax, Tx, ev);
        ev = fma2(nAy, Ty, ev);
    }

    float e0, e1;
    upk2(ev, e0, e1);
    reinterpret_cast<float2*>(out)[b * (HW / 2) + idx] = make_float2(e0, e1);
}

extern "C" void kernel_launch(void* const* d_in, const int* in_sizes, int n_in,
                              void* d_out, int out_size) {
    const float* x  = (const float*)d_in[0];   // (32, 16384, 2) float32
    const float* qs = (const float*)d_in[1];   // (32, 4, 2, 2, 3) float32
    float* out = (float*)d_out;                // (32, 16384) float32

    qprep<<<NB, 32>>>(qs);

    dim3 grid(HW / 512, NB);                   // 2 pixels per thread
    qmain_kernel<<<grid, 256>>>(x, out);
}

// round 6
// speedup vs baseline: 1.7694x; 1.1328x over previous
#include <cuda_runtime.h>
#include <cuda_bf16.h>

#define NB 32
#define HW 16384
#define NC 25

__device__ __forceinline__ float2 cmul(float2 a, float2 b) {
    return make_float2(fmaf(a.x, b.x, -a.y * b.y), fmaf(a.x, b.y, a.y * b.x));
}
__device__ __forceinline__ float2 cadd(float2 a, float2 b) {
    return make_float2(a.x + b.x, a.y + b.y);
}

// ---- f32x2 packed helpers ----
typedef unsigned long long u64;
__device__ __forceinline__ u64 pk2(float lo, float hi) {
    u64 r; asm("mov.b64 %0, {%1,%2};" : "=l"(r) : "f"(lo), "f"(hi)); return r;
}
__device__ __forceinline__ u64 fma2(u64 a, u64 b, u64 c) {
    u64 d; asm("fma.rn.f32x2 %0, %1, %2, %3;" : "=l"(d) : "l"(a), "l"(b), "l"(c)); return d;
}
__device__ __forceinline__ u64 mul2(u64 a, u64 b) {
    u64 d; asm("mul.rn.f32x2 %0, %1, %2;" : "=l"(d) : "l"(a), "l"(b)); return d;
}
__device__ __forceinline__ u64 add2(u64 a, u64 b) {
    u64 d; asm("add.rn.f32x2 %0, %1, %2;" : "=l"(d) : "l"(a), "l"(b)); return d;
}
__device__ __forceinline__ void upk2(u64 v, float& lo, float& hi) {
    asm("mov.b64 {%0,%1}, %2;" : "=f"(lo), "=f"(hi) : "l"(v));
}

// Evaluate the trig polynomial for a pixel pair packed in float4 (x0,x1 | x0,x1).
__device__ __forceinline__ u64 eval2(float4 xx, const u64* __restrict__ C) {
    float a0s, a0c, b0s, b0c, a1s, a1c, b1s, b1c;
    __sincosf(xx.x, &a0s, &a0c);
    __sincosf(xx.y, &b0s, &b0c);
    __sincosf(xx.z, &a1s, &a1c);
    __sincosf(xx.w, &b1s, &b1c);

    u64 A1x = pk2(a0c, a1c), A1y = pk2(a0s, a1s);
    u64 B1x = pk2(b0c, b1c), B1y = pk2(b0s, b1s);
    const u64 NEG1 = pk2(-1.0f, -1.0f);

    u64 nA1y = mul2(A1y, NEG1);
    u64 nB1y = mul2(B1y, NEG1);

    u64 A2x = fma2(A1x, A1x, mul2(A1y, nA1y));
    u64 tA  = mul2(A1x, A1y);
    u64 A2y = add2(tA, tA);
    u64 A3x = fma2(A2x, A1x, mul2(A2y, nA1y));
    u64 A3y = fma2(A2x, A1y, mul2(A2y, A1x));

    u64 B2x = fma2(B1x, B1x, mul2(B1y, nB1y));
    u64 tB  = mul2(B1x, B1y);
    u64 B2y = add2(tB, tB);
    u64 B3x = fma2(B2x, B1x, mul2(B2y, nB1y));
    u64 B3y = fma2(B2x, B1y, mul2(B2y, B1x));

    u64 nA2y = mul2(A2y, NEG1);
    u64 nA3y = mul2(A3y, NEG1);

    u64 ev = C[0];
    ev = fma2(C[1], B1x, ev);
    ev = fma2(C[2], B1y, ev);
    ev = fma2(C[3], B2x, ev);
    ev = fma2(C[4], B2y, ev);
    ev = fma2(C[5], B3x, ev);
    ev = fma2(C[6], B3y, ev);

#pragma unroll
    for (int mu4 = 0; mu4 < 3; mu4++) {
        const u64* R = C + 8 + mu4 * 16;
        u64 Tx = R[0];
        Tx = fma2(R[2],  B1x, Tx);
        Tx = fma2(R[4],  B1y, Tx);
        Tx = fma2(R[6],  B2x, Tx);
        Tx = fma2(R[8],  B2y, Tx);
        Tx = fma2(R[10], B3x, Tx);
        Tx = fma2(R[12], B3y, Tx);
        u64 Ty = R[1];
        Ty = fma2(R[3],  B1x, Ty);
        Ty = fma2(R[5],  B1y, Ty);
        Ty = fma2(R[7],  B2x, Ty);
        Ty = fma2(R[9],  B2y, Ty);
        Ty = fma2(R[11], B3x, Ty);
        Ty = fma2(R[13], B3y, Ty);

        u64 Ax  = (mu4 == 0) ? A1x  : (mu4 == 1) ? A2x  : A3x;
        u64 nAy = (mu4 == 0) ? nA1y : (mu4 == 1) ? nA2y : nA3y;
        ev = fma2(Ax, Tx, ev);
        ev = fma2(nAy, Ty, ev);
    }
    return ev;
}

// ---------------------------------------------------------------------------
// Fully fused kernel. grid = (16, NB), block = 128. Each block:
//   1. prefetches its 1024 pixels (4 x LDG.128 per thread, hidden under prep)
//   2. redundantly computes its b's 56 spectral constants in SHARED memory
//      (no global round-trip, no second kernel)
//   3. evaluates 8 px/thread as 4 f32x2 streams.
// ---------------------------------------------------------------------------
__global__ void __launch_bounds__(128)
qfused(const float* __restrict__ x, const float* __restrict__ qs,
       float* __restrict__ out) {
    __shared__ float2 sV[4];
    __shared__ float2 sU[3][4][4];
    __shared__ float2 sA[4][16];
    __shared__ float2 sP[4][NC];
    __shared__ float2 sCC[NC];
    __shared__ float2 sC2[56];

    const int b = blockIdx.y;
    const int t = threadIdx.x;
    const float2 zero = make_float2(0.0f, 0.0f);

    // ---- prefetch x (DRAM latency hides under prep) ----
    const int base = b * (HW / 2) + blockIdx.x * 512 + t;
    const float4* xin = reinterpret_cast<const float4*>(x);
    float4 xx0 = xin[base];
    float4 xx1 = xin[base + 128];
    float4 xx2 = xin[base + 256];
    float4 xx3 = xin[base + 384];

    // ---- Phase 1: ansatz-block unitaries, column-parallel (16 threads) ----
    if (t < 16) {
        const int s = t >> 2;
        const int c = t & 3;
        float2 col[4];
#pragma unroll
        for (int r = 0; r < 4; r++)
            col[r] = make_float2((r == c) ? 1.0f : 0.0f, 0.0f);

#pragma unroll
        for (int j = 0; j < 2; j++) {
#pragma unroll
            for (int k = 0; k < 2; k++) {
                const float* p = qs + ((((b * 4 + s) * 2 + j) * 2 + k) * 3);
                float th = p[0], ph = p[1], la = p[2];
                float ct = __cosf(th * 0.5f);
                float st = __sinf(th * 0.5f);
                float sl, cl, sp, cp;
                __sincosf(la, &sl, &cl);
                __sincosf(ph, &sp, &cp);
                float2 g00 = make_float2(ct, 0.0f);
                float2 g01 = make_float2(-cl * st, -sl * st);
                float2 g10 = make_float2(cp * st, sp * st);
                float2 epl = cmul(make_float2(cp, sp), make_float2(cl, sl));
                float2 g11 = make_float2(epl.x * ct, epl.y * ct);

                if (k == 0) {
                    float2 a0 = col[0], a1 = col[2];
                    col[0] = cadd(cmul(g00, a0), cmul(g01, a1));
                    col[2] = cadd(cmul(g10, a0), cmul(g11, a1));
                    float2 b0 = col[1], b1 = col[3];
                    col[1] = cadd(cmul(g00, b0), cmul(g01, b1));
                    col[3] = cadd(cmul(g10, b0), cmul(g11, b1));
                } else {
                    float2 a0 = col[0], a1 = col[1];
                    col[0] = cadd(cmul(g00, a0), cmul(g01, a1));
                    col[1] = cadd(cmul(g10, a0), cmul(g11, a1));
                    float2 b0 = col[2], b1 = col[3];
                    col[2] = cadd(cmul(g00, b0), cmul(g01, b1));
                    col[3] = cadd(cmul(g10, b0), cmul(g11, b1));
                }
            }
            // CNOT(ctrl = wire0): swap rows 2,3
            float2 tmp = col[2]; col[2] = col[3]; col[3] = tmp;
        }

        if (s == 0) {
            if (c == 0) {
#pragma unroll
                for (int r = 0; r < 4; r++) sV[r] = col[r];
            }
        } else {
#pragma unroll
            for (int r = 0; r < 4; r++) sU[s - 1][r][c] = col[r];
        }
    }
    __syncthreads();

    // ---- Phase 2: polynomial evolution (16 threads) ----
    {
        const int slot = t;
        const int m = slot >> 2;
        const int n = slot & 3;

        if (t < 16) {
#pragma unroll
            for (int r = 0; r < 4; r++)
                sA[r][slot] = (slot == 0) ? sV[r] : zero;
        }
        __syncthreads();

        for (int i = 0; i < 3; i++) {
            float2 sh0 = zero, sh1 = zero, sh2 = zero, sh3 = zero;
            if (t < 16) {
                sh0 = sA[0][slot];
                if (n >= 1) sh1 = sA[1][slot - 1];
                if (m >= 1) sh2 = sA[2][slot - 4];
                if (m >= 1 && n >= 1) sh3 = sA[3][slot - 5];
            }
            __syncthreads();
            if (t < 16) {
                float2 nv[4];
#pragma unroll
                for (int r = 0; r < 4; r++) {
                    float2 acc = cmul(sU[i][r][0], sh0);
                    acc = cadd(acc, cmul(sU[i][r][1], sh1));
                    acc = cadd(acc, cmul(sU[i][r][2], sh2));
                    acc = cadd(acc, cmul(sU[i][r][3], sh3));
                    nv[r] = acc;
                }
#pragma unroll
                for (int r = 0; r < 4; r++) sA[r][slot] = nv[r];
            }
            __syncthreads();
        }
    }

    // ---- Phase 3: spectral coefficients, r-parallel (4x25 threads) ----
    {
        const int r  = t >> 5;       // 0..3
        const int kk = t & 31;       // 0..31, active if < NC
        if (kk < NC) {
            int mu, nu;
            if (kk == 0)      { mu = 0; nu = 0; }
            else if (kk < 4)  { mu = 0; nu = kk; }
            else              { mu = 1 + (kk - 4) / 7; nu = (kk - 4) % 7 - 3; }

            int mlo = (mu > 0) ? mu : 0;
            int nlo = (nu > 0) ? nu : 0;
            int nhi = (nu < 0) ? (3 + nu) : 3;

            float sgn = (r < 2) ? 1.0f : -1.0f;
            float2 acc = zero;
            for (int mm = mlo; mm <= 3; mm++) {
                for (int nn = nlo; nn <= nhi; nn++) {
                    float2 a  = sA[r][mm * 4 + nn];
                    float2 bb = sA[r][(mm - mu) * 4 + (nn - nu)];
                    acc.x += sgn * (a.x * bb.x + a.y * bb.y);
                    acc.y += sgn * (a.y * bb.x - a.x * bb.y);
                }
            }
            sP[r][kk] = acc;
        }
        __syncthreads();
        if (t < NC) {
            float2 s0 = sP[0][t], s1 = sP[1][t], s2 = sP[2][t], s3 = sP[3][t];
            sCC[t] = make_float2(s0.x + s1.x + s2.x + s3.x,
                                 s0.y + s1.y + s2.y + s3.y);
        }
        __syncthreads();
    }

    // ---- Phase 4: sign-folded duplicated table (56 threads) ----
    if (t < 56) {
        const int idx = t;
        float v;
        if (idx == 0) {
            v = sCC[0].x;
        } else if (idx == 7) {
            v = 0.0f;
        } else if (idx < 7) {
            int k = (idx + 1) >> 1;
            v = (idx & 1) ? (2.0f * sCC[k].x) : (-2.0f * sCC[k].y);
        } else {
            int j = idx - 8;
            int mu4 = j >> 4;
            int r = j & 15;
            int cbase = 4 + mu4 * 7 + 3;   // index of c_{mu,0}
            if (r == 0)      v = 2.0f * sCC[cbase].x;
            else if (r == 1) v = 2.0f * sCC[cbase].y;
            else if (r < 14) {
                int nu = (r - 2) / 4 + 1;
                int type = (r - 2) & 3;
                float2 cp = sCC[cbase + nu], cm = sCC[cbase - nu];
                if (type == 0)      v = 2.0f * (cp.x + cm.x);
                else if (type == 1) v = 2.0f * (cp.y + cm.y);
                else if (type == 2) v = -2.0f * (cp.y - cm.y);
                else                v = 2.0f * (cp.x - cm.x);
            } else {
                v = 0.0f;
            }
        }
        sC2[idx] = make_float2(v, v);
    }
    __syncthreads();

    // ---- Main evaluation: 4 f32x2 streams (8 pixels) per thread ----
    const u64* C = (const u64*)sC2;
    u64 e0 = eval2(xx0, C);
    u64 e1 = eval2(xx1, C);
    u64 e2 = eval2(xx2, C);
    u64 e3 = eval2(xx3, C);

    float2* out2 = reinterpret_cast<float2*>(out);
    float lo, hi;
    upk2(e0, lo, hi); out2[base]       = make_float2(lo, hi);
    upk2(e1, lo, hi); out2[base + 128] = make_float2(lo, hi);
    upk2(e2, lo, hi); out2[base + 256] = make_float2(lo, hi);
    upk2(e3, lo, hi); out2[base + 384] = make_float2(lo, hi);
}

extern "C" void kernel_launch(void* const* d_in, const int* in_sizes, int n_in,
                              void* d_out, int out_size) {
    const float* x  = (const float*)d_in[0];   // (32, 16384, 2) float32
    const float* qs = (const float*)d_in[1];   // (32, 4, 2, 2, 3) float32
    float* out = (float*)d_out;                // (32, 16384) float32

    dim3 grid(16, NB);      // 512 blocks, 128 threads, 8 px/thread
    qfused<<<grid, 128>>>(x, qs, out);
}